// round 10
// baseline (speedup 1.0000x reference)
#include <cuda_runtime.h>
#include <cuda_bf16.h>
#include <math_constants.h>

// Problem shape (fixed by the dataset):
//   z_latents:  [128,32,32,64] f32  -> N = 131072 rows, D = 64
//   embeddings: [64,1024]      f32  -> D = 64, K = 1024
// Output: quantized_st (8388608 f32) then vq_loss (1 f32).

#define N_ROWS   131072
#define DIM      64
#define KCODES   1024
#define KCHUNK   128
#define THREADS  128
#define ROWS_CTA 512                       // 4 rows per thread
#define NBLOCKS  (N_ROWS / ROWS_CTA)       // 256
#define ZSTRIDE  516                       // words per d-plane (512 + 4 pad, 16B-aligned)

// Scratch (no allocations allowed):
__device__ float  g_cbT[KCODES * DIM];     // codebook transposed [K][D] for row gather
__device__ float  g_se[KCODES];            // sum_d e[d][k]^2 (square-then-add, ascending d)
__device__ double g_partials[NBLOCKS];     // per-CTA loss partial sums

// ---------------- packed f32x2 helpers ----------------
__device__ __forceinline__ unsigned long long ffma2(unsigned long long a,
                                                    unsigned long long b,
                                                    unsigned long long c) {
    unsigned long long d;
    asm("fma.rn.f32x2 %0, %1, %2, %3;" : "=l"(d) : "l"(a), "l"(b), "l"(c));
    return d;
}
// swap the two fp32 lanes of a u64 (register-pair reversal)
__device__ __forceinline__ unsigned long long swp(unsigned long long v) {
    unsigned long long r;
    asm("{\n\t.reg .b32 lo, hi;\n\tmov.b64 {lo,hi}, %1;\n\tmov.b64 %0, {hi,lo};\n\t}"
        : "=l"(r) : "l"(v));
    return r;
}
__device__ __forceinline__ float2 u2f2(unsigned long long v) {
    float2 f;
    asm("mov.b64 {%0, %1}, %2;" : "=f"(f.x), "=f"(f.y) : "l"(v));
    return f;
}

// ---------------- prep: transpose codebook + per-code squared norms ----------------
__global__ void vq_prep(const float* __restrict__ emb) {
    int k = blockIdx.x * blockDim.x + threadIdx.x;
    if (k < KCODES) {
        float s = 0.0f;
        #pragma unroll
        for (int d = 0; d < DIM; ++d) {
            float v = emb[d * KCODES + k];        // coalesced across k
            g_cbT[k * DIM + d] = v;
            s = __fadd_rn(s, __fmul_rn(v, v));    // square then add, ascending d
        }
        g_se[k] = s;
    }
}

// ---------------- main ----------------
// dynamic smem layout (floats):
//   zT  : [64][ZSTRIDE]  transposed z, rows of this CTA          33024 f
//   cbs : [64][KCHUNK]   codebook chunk, k-within-chunk major     8192 f
//   ses : [KCHUNK]                                                 128 f
//   szs : [ROWS_CTA]     per-row sum z^2                           512 f
//   wsm : 4 doubles                                                  8 f
#define ZT_OFF   0
#define CBS_OFF  (64 * ZSTRIDE)
#define SES_OFF  (CBS_OFF + 64 * KCHUNK)
#define SZS_OFF  (SES_OFF + KCHUNK)
#define WSM_OFF  (SZS_OFF + ROWS_CTA)
#define SMEM_BYTES ((WSM_OFF + 8) * 4)

__global__ void __launch_bounds__(THREADS, 1)
vq_main(const float* __restrict__ z,
        const float* __restrict__ emb,
        float* __restrict__ out)
{
    extern __shared__ float smem[];
    float*  zT  = smem + ZT_OFF;
    float*  cbs = smem + CBS_OFF;
    float*  ses = smem + SES_OFF;
    float*  szs = smem + SZS_OFF;
    double* wsm = (double*)(smem + WSM_OFF);

    const int b = blockIdx.x;
    const int t = threadIdx.x;

    // ---- stage: transpose this CTA's 512 z rows into zT[d][row]; per-row sz ----
    const float* zg = z + (size_t)b * ROWS_CTA * DIM;
    #pragma unroll
    for (int rr = 0; rr < 4; ++rr) {
        int r = t + rr * THREADS;                          // row within CTA
        const float4* zr4 = (const float4*)(zg + (size_t)r * DIM);
        float s = 0.0f;
        #pragma unroll
        for (int j = 0; j < 16; ++j) {
            float4 v = zr4[j];
            zT[(4 * j + 0) * ZSTRIDE + r] = v.x;           // conflict-free: bank = (r + c)%32
            zT[(4 * j + 1) * ZSTRIDE + r] = v.y;
            zT[(4 * j + 2) * ZSTRIDE + r] = v.z;
            zT[(4 * j + 3) * ZSTRIDE + r] = v.w;
            s = __fadd_rn(s, __fmul_rn(v.x, v.x));         // sequential ascending d
            s = __fadd_rn(s, __fmul_rn(v.y, v.y));
            s = __fadd_rn(s, __fmul_rn(v.z, v.z));
            s = __fadd_rn(s, __fmul_rn(v.w, v.w));
        }
        szs[r] = s;
    }
    __syncthreads();

    // this thread owns rows 4t .. 4t+3
    float sz[4];
    #pragma unroll
    for (int rr = 0; rr < 4; ++rr) sz[rr] = szs[4 * t + rr];

    float best[4] = {CUDART_INF_F, CUDART_INF_F, CUDART_INF_F, CUDART_INF_F};
    int   bi[4]   = {0, 0, 0, 0};

    const ulonglong2* zzp = (const ulonglong2*)(zT) ;      // indexed per-d below

    for (int k0 = 0; k0 < KCODES; k0 += KCHUNK) {
        __syncthreads();
        // load codebook chunk: cbs[d][kc], coalesced 512B rows
        #pragma unroll 4
        for (int i = t; i < DIM * KCHUNK; i += THREADS)
            cbs[i] = emb[(i >> 7) * KCODES + k0 + (i & (KCHUNK - 1))];
        ses[t] = g_se[k0 + t];
        __syncthreads();

        const ulonglong2* cb2base = (const ulonglong2*)cbs;   // 32 per d-row

        for (int kg = 0; kg < KCHUNK; kg += 8) {
            const ulonglong2* cb2 = cb2base + (kg >> 2);
            // accF/accR: [row-pair][code-pair]; fwd and swapped-e accumulators
            unsigned long long aF0[4] = {0,0,0,0}, aR0[4] = {0,0,0,0};
            unsigned long long aF1[4] = {0,0,0,0}, aR1[4] = {0,0,0,0};
            #pragma unroll
            for (int d = 0; d < DIM; ++d) {
                ulonglong2 zz = zzp[(d * ZSTRIDE) / 4 + t];   // (z0,z1),(z2,z3) rows 4t..4t+3
                ulonglong2 e0 = cb2[d * (KCHUNK / 4)];        // code pairs (kg,kg+1),(kg+2,kg+3)
                ulonglong2 e1 = cb2[d * (KCHUNK / 4) + 1];    // (kg+4,kg+5),(kg+6,kg+7)
                unsigned long long s0 = swp(e0.x), s1 = swp(e0.y);
                unsigned long long s2 = swp(e1.x), s3 = swp(e1.y);
                aF0[0] = ffma2(zz.x, e0.x, aF0[0]);  aR0[0] = ffma2(zz.x, s0, aR0[0]);
                aF0[1] = ffma2(zz.x, e0.y, aF0[1]);  aR0[1] = ffma2(zz.x, s1, aR0[1]);
                aF0[2] = ffma2(zz.x, e1.x, aF0[2]);  aR0[2] = ffma2(zz.x, s2, aR0[2]);
                aF0[3] = ffma2(zz.x, e1.y, aF0[3]);  aR0[3] = ffma2(zz.x, s3, aR0[3]);
                aF1[0] = ffma2(zz.y, e0.x, aF1[0]);  aR1[0] = ffma2(zz.y, s0, aR1[0]);
                aF1[1] = ffma2(zz.y, e0.y, aF1[1]);  aR1[1] = ffma2(zz.y, s1, aR1[1]);
                aF1[2] = ffma2(zz.y, e1.x, aF1[2]);  aR1[2] = ffma2(zz.y, s2, aR1[2]);
                aF1[3] = ffma2(zz.y, e1.y, aF1[3]);  aR1[3] = ffma2(zz.y, s3, aR1[3]);
            }
            // unpack: per code pair q, lanes give the 4 cross dot-products
            float2 f0[4], r0[4], f1[4], r1[4];
            #pragma unroll
            for (int q = 0; q < 4; ++q) {
                f0[q] = u2f2(aF0[q]);  r0[q] = u2f2(aR0[q]);
                f1[q] = u2f2(aF1[q]);  r1[q] = u2f2(aR1[q]);
            }
            // ascending code order, strict < (first-occurrence tie-break)
            #pragma unroll
            for (int j = 0; j < 8; ++j) {
                int   q   = j >> 1;
                bool  odd = j & 1;
                float se  = ses[kg + j];
                int   kk  = k0 + kg + j;
                // dot(row, code kk): fwd lane-lo = even row/even code, etc.
                float d0 = odd ? r0[q].x : f0[q].x;   // row 4t+0
                float d1 = odd ? f0[q].y : r0[q].y;   // row 4t+1
                float d2 = odd ? r1[q].x : f1[q].x;   // row 4t+2
                float d3 = odd ? f1[q].y : r1[q].y;   // row 4t+3
                float q0 = __fadd_rn(__fsub_rn(sz[0], __fmul_rn(2.0f, d0)), se);
                float q1 = __fadd_rn(__fsub_rn(sz[1], __fmul_rn(2.0f, d1)), se);
                float q2 = __fadd_rn(__fsub_rn(sz[2], __fmul_rn(2.0f, d2)), se);
                float q3 = __fadd_rn(__fsub_rn(sz[3], __fmul_rn(2.0f, d3)), se);
                if (q0 < best[0]) { best[0] = q0; bi[0] = kk; }
                if (q1 < best[1]) { best[1] = q1; bi[1] = kk; }
                if (q2 < best[2]) { best[2] = q2; bi[2] = kk; }
                if (q3 < best[3]) { best[3] = q3; bi[3] = kk; }
            }
        }
    }

    // ---- gather chosen rows, straight-through output, loss partial ----
    double lsum = 0.0;
    #pragma unroll
    for (int rr = 0; rr < 4; ++rr) {
        int r = 4 * t + rr;
        const float4* qrow = (const float4*)(g_cbT + (size_t)bi[rr] * DIM);
        float4* orow = (float4*)(out + ((size_t)b * ROWS_CTA + r) * DIM);
        #pragma unroll
        for (int j = 0; j < DIM / 4; ++j) {
            float4 q4 = qrow[j];
            float z0 = zT[(4 * j + 0) * ZSTRIDE + r];
            float z1 = zT[(4 * j + 1) * ZSTRIDE + r];
            float z2 = zT[(4 * j + 2) * ZSTRIDE + r];
            float z3 = zT[(4 * j + 3) * ZSTRIDE + r];
            float4 o4;
            float d0 = __fsub_rn(q4.x, z0);  o4.x = __fadd_rn(z0, d0);
            float d1 = __fsub_rn(q4.y, z1);  o4.y = __fadd_rn(z1, d1);
            float d2 = __fsub_rn(q4.z, z2);  o4.z = __fadd_rn(z2, d2);
            float d3 = __fsub_rn(q4.w, z3);  o4.w = __fadd_rn(z3, d3);
            lsum += (double)__fmul_rn(d0, d0) + (double)__fmul_rn(d1, d1)
                  + (double)__fmul_rn(d2, d2) + (double)__fmul_rn(d3, d3);
            orow[j] = o4;
        }
    }

    // deterministic block reduction (4 warps)
    #pragma unroll
    for (int o = 16; o > 0; o >>= 1)
        lsum += __shfl_down_sync(0xffffffffu, lsum, o);
    if ((t & 31) == 0) wsm[t >> 5] = lsum;
    __syncthreads();
    if (t == 0) {
        double s = 0.0;
        #pragma unroll
        for (int w = 0; w < THREADS / 32; ++w) s += wsm[w];
        g_partials[b] = s;
    }
}

// ---------------- finish: reduce partials, emit vq_loss ----------------
__global__ void vq_finish(float* __restrict__ out) {
    __shared__ double sm[256];
    int t = threadIdx.x;
    sm[t] = g_partials[t];                 // NBLOCKS == 256
    __syncthreads();
    #pragma unroll
    for (int s = 128; s > 0; s >>= 1) {
        if (t < s) sm[t] += sm[t + s];
        __syncthreads();
    }
    if (t == 0) {
        float L = (float)(sm[0] / (double)(N_ROWS * DIM));
        out[N_ROWS * DIM] = __fadd_rn(L, __fmul_rn(0.25f, L));
    }
}

extern "C" void kernel_launch(void* const* d_in, const int* in_sizes, int n_in,
                              void* d_out, int out_size) {
    const float* z   = (const float*)d_in[0];
    const float* emb = (const float*)d_in[1];
    float* out = (float*)d_out;

    (void)in_sizes; (void)n_in; (void)out_size;

    cudaFuncSetAttribute(vq_main, cudaFuncAttributeMaxDynamicSharedMemorySize, SMEM_BYTES);

    vq_prep<<<(KCODES + 255) / 256, 256>>>(emb);
    vq_main<<<NBLOCKS, THREADS, SMEM_BYTES>>>(z, emb, out);
    vq_finish<<<1, 256>>>(out);
}

// round 11
// speedup vs baseline: 1.5460x; 1.5460x over previous
#include <cuda_runtime.h>
#include <cuda_bf16.h>
#include <math_constants.h>

// Problem shape (fixed by the dataset):
//   z_latents:  [128,32,32,64] f32  -> N = 131072 rows, D = 64
//   embeddings: [64,1024]      f32  -> D = 64, K = 1024
// Output: quantized_st (8388608 f32) then vq_loss (1 f32) -> 8388609 elements.

#define N_ROWS   131072
#define DIM      64
#define KCODES   1024
#define KCHUNK   128
#define KGROUP   16
#define THREADS  256
#define ROWS_CTA 256
#define NBLOCKS  (N_ROWS / ROWS_CTA)   // 512

__device__ double g_partials[NBLOCKS];   // per-CTA loss partial sums

// ---------------- packed f32x2 helpers ----------------
__device__ __forceinline__ unsigned long long pk2(float lo, float hi) {
    unsigned long long r;
    asm("mov.b64 %0, {%1, %2};" : "=l"(r) : "f"(lo), "f"(hi));
    return r;
}
__device__ __forceinline__ float2 u2f2(unsigned long long v) {
    float2 f;
    asm("mov.b64 {%0, %1}, %2;" : "=f"(f.x), "=f"(f.y) : "l"(v));
    return f;
}
__device__ __forceinline__ unsigned long long ffma2(unsigned long long a,
                                                    unsigned long long b,
                                                    unsigned long long c) {
    unsigned long long d;
    asm("fma.rn.f32x2 %0, %1, %2, %3;" : "=l"(d) : "l"(a), "l"(b), "l"(c));
    return d;
}

// ---------------- main ----------------
// dynamic smem (floats):
//   zsm : ROWS_CTA * 65   padded z rows                 16640 f (66560 B)
//   cbs : DIM * KCHUNK    codebook chunk, k-major        8192 f (32768 B)
//   ses : KCHUNK          per-code sum e^2                128 f
//   wsm : 8 doubles                                        16 f
#define ZSM_OFF  0
#define CBS_OFF  (ROWS_CTA * 65)
#define SES_OFF  (CBS_OFF + DIM * KCHUNK)
#define WSM_OFF  (SES_OFF + KCHUNK)
#define SMEM_BYTES ((WSM_OFF + 16) * 4)

__global__ void __launch_bounds__(THREADS, 2)
vq_main(const float* __restrict__ z,
        const float* __restrict__ emb,
        float* __restrict__ out)
{
    extern __shared__ float smem[];
    float*  zsm = smem + ZSM_OFF;
    float*  cbs = smem + CBS_OFF;
    float*  ses = smem + SES_OFF;
    double* wsm = (double*)(smem + WSM_OFF);

    const int b = blockIdx.x;
    const int t = threadIdx.x;

    // ---- stage this CTA's 256 z rows into smem (coalesced) ----
    const float* zg = z + (size_t)b * ROWS_CTA * DIM;
    #pragma unroll 4
    for (int i = t; i < ROWS_CTA * DIM; i += THREADS) {
        int r = i >> 6, d = i & 63;
        zsm[r * 65 + d] = zg[i];
    }
    __syncthreads();

    // thread t owns row t; zr in registers, conflict-free LDS (bank=(t+d)%32)
    float zr[DIM];
    #pragma unroll
    for (int d = 0; d < DIM; ++d) zr[d] = zsm[t * 65 + d];

    // s_z: square then add, ascending d (matches reference elementwise+reduce)
    float sz = 0.0f;
    #pragma unroll
    for (int d = 0; d < DIM; ++d) sz = __fadd_rn(sz, __fmul_rn(zr[d], zr[d]));

    float best = CUDART_INF_F;
    int   bidx = 0;

    for (int k0 = 0; k0 < KCODES; k0 += KCHUNK) {
        __syncthreads();
        // stage codebook chunk cbs[d][kc] (coalesced 512B rows, L2-resident)
        #pragma unroll 4
        for (int i = t; i < DIM * KCHUNK; i += THREADS)
            cbs[i] = emb[(i >> 7) * KCODES + k0 + (i & (KCHUNK - 1))];
        __syncthreads();

        // per-code squared norms from the staged chunk: sequential ascending d
        if (t < KCHUNK) {
            float s = 0.0f;
            #pragma unroll
            for (int d = 0; d < DIM; ++d) {
                float v = cbs[d * KCHUNK + t];
                s = __fadd_rn(s, __fmul_rn(v, v));
            }
            ses[t] = s;
        }
        __syncthreads();

        const ulonglong2* cb2base = (const ulonglong2*)cbs;   // 32 per d-row

        #pragma unroll 1                       // keep hot loop L1.5-resident
        for (int kg = 0; kg < KCHUNK; kg += KGROUP) {
            const ulonglong2* cb2 = cb2base + (kg >> 2);
            unsigned long long acc[KGROUP / 2];
            #pragma unroll
            for (int q = 0; q < KGROUP / 2; ++q) acc[q] = 0ull;

            #pragma unroll
            for (int d = 0; d < DIM; ++d) {
                ulonglong2 e01 = cb2[d * (KCHUNK / 4) + 0];   // codes kg+0..3 (broadcast)
                ulonglong2 e23 = cb2[d * (KCHUNK / 4) + 1];   // kg+4..7
                ulonglong2 e45 = cb2[d * (KCHUNK / 4) + 2];   // kg+8..11
                ulonglong2 e67 = cb2[d * (KCHUNK / 4) + 3];   // kg+12..15
                unsigned long long zz = pk2(zr[d], zr[d]);
                acc[0] = ffma2(zz, e01.x, acc[0]);            // sequential fp32 chain per code
                acc[1] = ffma2(zz, e01.y, acc[1]);
                acc[2] = ffma2(zz, e23.x, acc[2]);
                acc[3] = ffma2(zz, e23.y, acc[3]);
                acc[4] = ffma2(zz, e45.x, acc[4]);
                acc[5] = ffma2(zz, e45.y, acc[5]);
                acc[6] = ffma2(zz, e67.x, acc[6]);
                acc[7] = ffma2(zz, e67.y, acc[7]);
            }

            float dot[KGROUP];
            #pragma unroll
            for (int q = 0; q < KGROUP / 2; ++q) {
                float2 f = u2f2(acc[q]);
                dot[2 * q]     = f.x;
                dot[2 * q + 1] = f.y;
            }
            // ascending code order, strict < => first-occurrence tie-break
            #pragma unroll
            for (int j = 0; j < KGROUP; ++j) {
                float dist = __fadd_rn(__fsub_rn(sz, __fmul_rn(2.0f, dot[j])),
                                       ses[kg + j]);
                int kk = k0 + kg + j;
                if (dist < best) { best = dist; bidx = kk; }
            }
        }
    }

    // ---- gather chosen code (stride-K reads, emb is L2-resident),
    //      straight-through output, loss partial ----
    double lsum = 0.0;
    float4* orow = (float4*)(out + ((size_t)b * ROWS_CTA + t) * DIM);
    #pragma unroll
    for (int j = 0; j < DIM / 4; ++j) {
        float q0 = __ldg(emb + (4 * j + 0) * KCODES + bidx);
        float q1 = __ldg(emb + (4 * j + 1) * KCODES + bidx);
        float q2 = __ldg(emb + (4 * j + 2) * KCODES + bidx);
        float q3 = __ldg(emb + (4 * j + 3) * KCODES + bidx);
        float z0 = zr[4 * j + 0], z1 = zr[4 * j + 1];
        float z2 = zr[4 * j + 2], z3 = zr[4 * j + 3];
        float4 o4;
        float d0 = __fsub_rn(q0, z0);  o4.x = __fadd_rn(z0, d0);
        float d1 = __fsub_rn(q1, z1);  o4.y = __fadd_rn(z1, d1);
        float d2 = __fsub_rn(q2, z2);  o4.z = __fadd_rn(z2, d2);
        float d3 = __fsub_rn(q3, z3);  o4.w = __fadd_rn(z3, d3);
        lsum += (double)__fmul_rn(d0, d0) + (double)__fmul_rn(d1, d1)
              + (double)__fmul_rn(d2, d2) + (double)__fmul_rn(d3, d3);
        orow[j] = o4;
    }

    // deterministic block reduction of lsum (double)
    #pragma unroll
    for (int o = 16; o > 0; o >>= 1)
        lsum += __shfl_down_sync(0xffffffffu, lsum, o);
    if ((t & 31) == 0) wsm[t >> 5] = lsum;
    __syncthreads();
    if (t == 0) {
        double s = 0.0;
        #pragma unroll
        for (int w = 0; w < THREADS / 32; ++w) s += wsm[w];
        g_partials[b] = s;
    }
}

// ---------------- finish: reduce partials, emit vq_loss ----------------
__global__ void vq_finish(float* __restrict__ out) {
    __shared__ double sm[256];
    int t = threadIdx.x;
    sm[t] = g_partials[t] + g_partials[t + 256];   // NBLOCKS == 512
    __syncthreads();
    #pragma unroll
    for (int s = 128; s > 0; s >>= 1) {
        if (t < s) sm[t] += sm[t + s];
        __syncthreads();
    }
    if (t == 0) {
        float L = (float)(sm[0] / (double)(N_ROWS * DIM));
        // vq_loss = embedding_loss + 0.25 * commitment_loss (numerically equal)
        out[N_ROWS * DIM] = __fadd_rn(L, __fmul_rn(0.25f, L));
    }
}

extern "C" void kernel_launch(void* const* d_in, const int* in_sizes, int n_in,
                              void* d_out, int out_size) {
    const float* z   = (const float*)d_in[0];
    const float* emb = (const float*)d_in[1];
    float* out = (float*)d_out;

    (void)in_sizes; (void)n_in; (void)out_size;

    cudaFuncSetAttribute(vq_main, cudaFuncAttributeMaxDynamicSharedMemorySize, SMEM_BYTES);

    vq_main<<<NBLOCKS, THREADS, SMEM_BYTES>>>(z, emb, out);
    vq_finish<<<1, 256>>>(out);
}

// round 12
// speedup vs baseline: 1.5460x; 1.0001x over previous
#include <cuda_runtime.h>
#include <cuda_bf16.h>
#include <math_constants.h>

// Problem shape (fixed by the dataset):
//   z_latents:  [128,32,32,64] f32  -> N = 131072 rows, D = 64
//   embeddings: [64,1024]      f32  -> D = 64, K = 1024
// Output: quantized_st (8388608 f32) then vq_loss (1 f32) -> 8388609 elements.

#define N_ROWS   131072
#define DIM      64
#define KCODES   1024
#define KCHUNK   128
#define KGROUP   16
#define THREADS  256
#define ROWS_CTA 256
#define NBLOCKS  (N_ROWS / ROWS_CTA)   // 512

__device__ double g_partials[NBLOCKS];   // per-CTA loss partial sums

// ---------------- packed f32x2 helpers ----------------
__device__ __forceinline__ unsigned long long pk2(float lo, float hi) {
    unsigned long long r;
    asm("mov.b64 %0, {%1, %2};" : "=l"(r) : "f"(lo), "f"(hi));
    return r;
}
__device__ __forceinline__ float2 u2f2(unsigned long long v) {
    float2 f;
    asm("mov.b64 {%0, %1}, %2;" : "=f"(f.x), "=f"(f.y) : "l"(v));
    return f;
}
__device__ __forceinline__ unsigned long long ffma2(unsigned long long a,
                                                    unsigned long long b,
                                                    unsigned long long c) {
    unsigned long long d;
    asm("fma.rn.f32x2 %0, %1, %2, %3;" : "=l"(d) : "l"(a), "l"(b), "l"(c));
    return d;
}

// ---------------- main ----------------
// dynamic smem (floats):
//   zsm : ROWS_CTA * 65   padded z rows                 16640 f (66560 B)
//   cbs : DIM * KCHUNK    codebook chunk, k-major        8192 f (32768 B)
//   ses : KCHUNK          per-code sum e^2                128 f
//   wsm : 8 doubles                                        16 f
#define ZSM_OFF  0
#define CBS_OFF  (ROWS_CTA * 65)
#define SES_OFF  (CBS_OFF + DIM * KCHUNK)
#define WSM_OFF  (SES_OFF + KCHUNK)
#define SMEM_BYTES ((WSM_OFF + 16) * 4)

__global__ void __launch_bounds__(THREADS, 2)
vq_main(const float* __restrict__ z,
        const float* __restrict__ emb,
        float* __restrict__ out)
{
    extern __shared__ float smem[];
    float*  zsm = smem + ZSM_OFF;
    float*  cbs = smem + CBS_OFF;
    float*  ses = smem + SES_OFF;
    double* wsm = (double*)(smem + WSM_OFF);

    const int b = blockIdx.x;
    const int t = threadIdx.x;

    // ---- stage this CTA's 256 z rows into smem (coalesced) ----
    const float* zg = z + (size_t)b * ROWS_CTA * DIM;
    #pragma unroll 4
    for (int i = t; i < ROWS_CTA * DIM; i += THREADS) {
        int r = i >> 6, d = i & 63;
        zsm[r * 65 + d] = zg[i];
    }
    __syncthreads();

    // thread t owns row t; zr in registers, conflict-free LDS (bank=(t+d)%32)
    float zr[DIM];
    #pragma unroll
    for (int d = 0; d < DIM; ++d) zr[d] = zsm[t * 65 + d];

    // s_z: square then add, ascending d (matches reference elementwise+reduce)
    float sz = 0.0f;
    #pragma unroll
    for (int d = 0; d < DIM; ++d) sz = __fadd_rn(sz, __fmul_rn(zr[d], zr[d]));

    float best = CUDART_INF_F;
    int   bidx = 0;

    for (int k0 = 0; k0 < KCODES; k0 += KCHUNK) {
        __syncthreads();
        // stage codebook chunk cbs[d][kc] (coalesced 512B rows, L2-resident)
        #pragma unroll 4
        for (int i = t; i < DIM * KCHUNK; i += THREADS)
            cbs[i] = emb[(i >> 7) * KCODES + k0 + (i & (KCHUNK - 1))];
        __syncthreads();

        // per-code squared norms from the staged chunk: sequential ascending d
        if (t < KCHUNK) {
            float s = 0.0f;
            #pragma unroll
            for (int d = 0; d < DIM; ++d) {
                float v = cbs[d * KCHUNK + t];
                s = __fadd_rn(s, __fmul_rn(v, v));
            }
            ses[t] = s;
        }
        __syncthreads();

        const ulonglong2* cb2base = (const ulonglong2*)cbs;   // 32 per d-row

        #pragma unroll 1                       // keep hot loop L1.5-resident
        for (int kg = 0; kg < KCHUNK; kg += KGROUP) {
            const ulonglong2* cb2 = cb2base + (kg >> 2);
            unsigned long long acc[KGROUP / 2];
            #pragma unroll
            for (int q = 0; q < KGROUP / 2; ++q) acc[q] = 0ull;

            #pragma unroll
            for (int d = 0; d < DIM; ++d) {
                ulonglong2 e01 = cb2[d * (KCHUNK / 4) + 0];   // codes kg+0..3 (broadcast)
                ulonglong2 e23 = cb2[d * (KCHUNK / 4) + 1];   // kg+4..7
                ulonglong2 e45 = cb2[d * (KCHUNK / 4) + 2];   // kg+8..11
                ulonglong2 e67 = cb2[d * (KCHUNK / 4) + 3];   // kg+12..15
                unsigned long long zz = pk2(zr[d], zr[d]);
                acc[0] = ffma2(zz, e01.x, acc[0]);            // sequential fp32 chain per code
                acc[1] = ffma2(zz, e01.y, acc[1]);
                acc[2] = ffma2(zz, e23.x, acc[2]);
                acc[3] = ffma2(zz, e23.y, acc[3]);
                acc[4] = ffma2(zz, e45.x, acc[4]);
                acc[5] = ffma2(zz, e45.y, acc[5]);
                acc[6] = ffma2(zz, e67.x, acc[6]);
                acc[7] = ffma2(zz, e67.y, acc[7]);
            }

            float dot[KGROUP];
            #pragma unroll
            for (int q = 0; q < KGROUP / 2; ++q) {
                float2 f = u2f2(acc[q]);
                dot[2 * q]     = f.x;
                dot[2 * q + 1] = f.y;
            }
            // ascending code order, strict < => first-occurrence tie-break
            #pragma unroll
            for (int j = 0; j < KGROUP; ++j) {
                float dist = __fadd_rn(__fsub_rn(sz, __fmul_rn(2.0f, dot[j])),
                                       ses[kg + j]);
                int kk = k0 + kg + j;
                if (dist < best) { best = dist; bidx = kk; }
            }
        }
    }

    // ---- gather chosen code (stride-K reads, emb is L2-resident),
    //      straight-through output, loss partial ----
    double lsum = 0.0;
    float4* orow = (float4*)(out + ((size_t)b * ROWS_CTA + t) * DIM);
    #pragma unroll
    for (int j = 0; j < DIM / 4; ++j) {
        float q0 = __ldg(emb + (4 * j + 0) * KCODES + bidx);
        float q1 = __ldg(emb + (4 * j + 1) * KCODES + bidx);
        float q2 = __ldg(emb + (4 * j + 2) * KCODES + bidx);
        float q3 = __ldg(emb + (4 * j + 3) * KCODES + bidx);
        float z0 = zr[4 * j + 0], z1 = zr[4 * j + 1];
        float z2 = zr[4 * j + 2], z3 = zr[4 * j + 3];
        float4 o4;
        float d0 = __fsub_rn(q0, z0);  o4.x = __fadd_rn(z0, d0);
        float d1 = __fsub_rn(q1, z1);  o4.y = __fadd_rn(z1, d1);
        float d2 = __fsub_rn(q2, z2);  o4.z = __fadd_rn(z2, d2);
        float d3 = __fsub_rn(q3, z3);  o4.w = __fadd_rn(z3, d3);
        lsum += (double)__fmul_rn(d0, d0) + (double)__fmul_rn(d1, d1)
              + (double)__fmul_rn(d2, d2) + (double)__fmul_rn(d3, d3);
        orow[j] = o4;
    }

    // deterministic block reduction of lsum (double)
    #pragma unroll
    for (int o = 16; o > 0; o >>= 1)
        lsum += __shfl_down_sync(0xffffffffu, lsum, o);
    if ((t & 31) == 0) wsm[t >> 5] = lsum;
    __syncthreads();
    if (t == 0) {
        double s = 0.0;
        #pragma unroll
        for (int w = 0; w < THREADS / 32; ++w) s += wsm[w];
        g_partials[b] = s;
    }
}

// ---------------- finish: reduce partials, emit vq_loss ----------------
__global__ void vq_finish(float* __restrict__ out) {
    __shared__ double sm[256];
    int t = threadIdx.x;
    sm[t] = g_partials[t] + g_partials[t + 256];   // NBLOCKS == 512
    __syncthreads();
    #pragma unroll
    for (int s = 128; s > 0; s >>= 1) {
        if (t < s) sm[t] += sm[t + s];
        __syncthreads();
    }
    if (t == 0) {
        float L = (float)(sm[0] / (double)(N_ROWS * DIM));
        // vq_loss = embedding_loss + 0.25 * commitment_loss (numerically equal)
        out[N_ROWS * DIM] = __fadd_rn(L, __fmul_rn(0.25f, L));
    }
}

extern "C" void kernel_launch(void* const* d_in, const int* in_sizes, int n_in,
                              void* d_out, int out_size) {
    const float* z   = (const float*)d_in[0];
    const float* emb = (const float*)d_in[1];
    float* out = (float*)d_out;

    (void)in_sizes; (void)n_in; (void)out_size;

    cudaFuncSetAttribute(vq_main, cudaFuncAttributeMaxDynamicSharedMemorySize, SMEM_BYTES);

    vq_main<<<NBLOCKS, THREADS, SMEM_BYTES>>>(z, emb, out);
    vq_finish<<<1, 256>>>(out);
}

// round 13
// speedup vs baseline: 2.1564x; 1.3948x over previous
#include <cuda_runtime.h>
#include <cuda_bf16.h>
#include <math_constants.h>

// Problem shape (fixed by the dataset):
//   z_latents:  [128,32,32,64] f32  -> N = 131072 rows, D = 64
//   embeddings: [64,1024]      f32  -> D = 64, K = 1024
// Output: quantized_st (8388608 f32) then vq_loss (1 f32) -> 8388609 elements.

#define N_ROWS   131072
#define DIM      64
#define KCODES   1024
#define KCHUNK   128
#define THREADS  128
#define ROWS_CTA 256                      // 2 rows per thread
#define NBLOCKS  (N_ROWS / ROWS_CTA)      // 512

__device__ double g_partials[NBLOCKS];    // per-CTA loss partial sums

// ---------------- packed f32x2 helpers ----------------
__device__ __forceinline__ unsigned long long pk2(float lo, float hi) {
    unsigned long long r;
    asm("mov.b64 %0, {%1, %2};" : "=l"(r) : "f"(lo), "f"(hi));
    return r;
}
__device__ __forceinline__ float2 u2f2(unsigned long long v) {
    float2 f;
    asm("mov.b64 {%0, %1}, %2;" : "=f"(f.x), "=f"(f.y) : "l"(v));
    return f;
}
__device__ __forceinline__ unsigned long long ffma2(unsigned long long a,
                                                    unsigned long long b,
                                                    unsigned long long c) {
    unsigned long long d;
    asm("fma.rn.f32x2 %0, %1, %2, %3;" : "=l"(d) : "l"(a), "l"(b), "l"(c));
    return d;
}

// ---------------- main ----------------
// dynamic smem (floats):
//   cbs : DIM * KCHUNK   codebook chunk, k-major   8192 f (32768 B)
//   ses : KCHUNK         per-code sum e^2           128 f
//   wsm : 4 doubles                                   8 f
#define CBS_OFF  0
#define SES_OFF  (DIM * KCHUNK)
#define WSM_OFF  (SES_OFF + KCHUNK)
#define SMEM_BYTES ((WSM_OFF + 8) * 4)

__global__ void __launch_bounds__(THREADS, 2)
vq_main(const float* __restrict__ z,
        const float* __restrict__ emb,
        float* __restrict__ out)
{
    extern __shared__ float smem[];
    float*  cbs = smem + CBS_OFF;
    float*  ses = smem + SES_OFF;
    double* wsm = (double*)(smem + WSM_OFF);

    const int b = blockIdx.x;
    const int t = threadIdx.x;

    // ---- load this thread's two z rows (2t, 2t+1) straight into registers ----
    const float* zg = z + (size_t)b * ROWS_CTA * DIM;
    float zr0[DIM], zr1[DIM];
    {
        const float4* p0 = (const float4*)(zg + (size_t)(2 * t)     * DIM);
        const float4* p1 = (const float4*)(zg + (size_t)(2 * t + 1) * DIM);
        #pragma unroll
        for (int j = 0; j < DIM / 4; ++j) {
            float4 a = p0[j];
            zr0[4*j+0] = a.x; zr0[4*j+1] = a.y; zr0[4*j+2] = a.z; zr0[4*j+3] = a.w;
            float4 c = p1[j];
            zr1[4*j+0] = c.x; zr1[4*j+1] = c.y; zr1[4*j+2] = c.z; zr1[4*j+3] = c.w;
        }
    }

    // s_z per row: square then add, ascending d (matches reference)
    float sz0 = 0.0f, sz1 = 0.0f;
    #pragma unroll
    for (int d = 0; d < DIM; ++d) {
        sz0 = __fadd_rn(sz0, __fmul_rn(zr0[d], zr0[d]));
        sz1 = __fadd_rn(sz1, __fmul_rn(zr1[d], zr1[d]));
    }

    float best0 = CUDART_INF_F, best1 = CUDART_INF_F;
    int   bi0 = 0, bi1 = 0;

    for (int k0 = 0; k0 < KCODES; k0 += KCHUNK) {
        __syncthreads();
        // stage codebook chunk cbs[d][kc] with float4 copies (coalesced, L2-resident)
        {
            float4* dst = (float4*)cbs;
            #pragma unroll
            for (int i = 0; i < (DIM * KCHUNK / 4) / THREADS; ++i) {
                int idx = i * THREADS + t;              // float4 index
                int d   = idx >> 5;                     // 32 float4 per d-row
                int kc4 = idx & 31;
                dst[idx] = *(const float4*)(emb + (size_t)d * KCODES + k0 + 4 * kc4);
            }
        }
        __syncthreads();

        // per-code squared norms from the staged chunk: sequential ascending d
        {
            float s = 0.0f;
            #pragma unroll
            for (int d = 0; d < DIM; ++d) {
                float v = cbs[d * KCHUNK + t];          // conflict-free
                s = __fadd_rn(s, __fmul_rn(v, v));
            }
            ses[t] = s;
        }
        __syncthreads();

        const ulonglong2* cb2base = (const ulonglong2*)cbs;   // 32 per d-row

        #pragma unroll 1                                // keep hot loop I$-resident
        for (int kg = 0; kg < KCHUNK; kg += 8) {
            const ulonglong2* cb2 = cb2base + (kg >> 2);
            // aF[q]: zzA=(z0,z1) x (e_{2q}, e_{2q+1}) -> (dot(r0,2q), dot(r1,2q+1))
            // aS[q]: zzB=(z1,z0) x (e_{2q}, e_{2q+1}) -> (dot(r1,2q), dot(r0,2q+1))
            unsigned long long aF[4] = {0,0,0,0}, aS[4] = {0,0,0,0};
            #pragma unroll
            for (int d = 0; d < DIM; ++d) {
                ulonglong2 e01 = cb2[d * (KCHUNK / 4) + 0];   // codes kg..kg+3 (broadcast)
                ulonglong2 e23 = cb2[d * (KCHUNK / 4) + 1];   // codes kg+4..kg+7
                unsigned long long zzA = pk2(zr0[d], zr1[d]);
                unsigned long long zzB = pk2(zr1[d], zr0[d]);
                aF[0] = ffma2(zzA, e01.x, aF[0]);  aS[0] = ffma2(zzB, e01.x, aS[0]);
                aF[1] = ffma2(zzA, e01.y, aF[1]);  aS[1] = ffma2(zzB, e01.y, aS[1]);
                aF[2] = ffma2(zzA, e23.x, aF[2]);  aS[2] = ffma2(zzB, e23.x, aS[2]);
                aF[3] = ffma2(zzA, e23.y, aF[3]);  aS[3] = ffma2(zzB, e23.y, aS[3]);
            }
            // ascending code order, strict < => first-occurrence tie-break
            #pragma unroll
            for (int q = 0; q < 4; ++q) {
                float2 f = u2f2(aF[q]);
                float2 s = u2f2(aS[q]);
                int   kkA = k0 + kg + 2 * q;
                float seA = ses[kg + 2 * q];
                float seB = ses[kg + 2 * q + 1];
                // code kkA: row0 -> f.x, row1 -> s.x
                float dA0 = __fadd_rn(__fsub_rn(sz0, __fmul_rn(2.0f, f.x)), seA);
                float dA1 = __fadd_rn(__fsub_rn(sz1, __fmul_rn(2.0f, s.x)), seA);
                if (dA0 < best0) { best0 = dA0; bi0 = kkA; }
                if (dA1 < best1) { best1 = dA1; bi1 = kkA; }
                // code kkA+1: row0 -> s.y, row1 -> f.y
                float dB0 = __fadd_rn(__fsub_rn(sz0, __fmul_rn(2.0f, s.y)), seB);
                float dB1 = __fadd_rn(__fsub_rn(sz1, __fmul_rn(2.0f, f.y)), seB);
                if (dB0 < best0) { best0 = dB0; bi0 = kkA + 1; }
                if (dB1 < best1) { best1 = dB1; bi1 = kkA + 1; }
            }
        }
    }

    // ---- gather chosen codes (emb is L2-resident), ST output, loss partial ----
    double lsum = 0.0;
    {
        float4* orow0 = (float4*)(out + ((size_t)b * ROWS_CTA + 2 * t)     * DIM);
        float4* orow1 = (float4*)(out + ((size_t)b * ROWS_CTA + 2 * t + 1) * DIM);
        #pragma unroll
        for (int j = 0; j < DIM / 4; ++j) {
            float4 o0, o1;
            #pragma unroll
            for (int c = 0; c < 4; ++c) {
                int d = 4 * j + c;
                float q0 = __ldg(emb + (size_t)d * KCODES + bi0);
                float q1 = __ldg(emb + (size_t)d * KCODES + bi1);
                float e0 = __fsub_rn(q0, zr0[d]);
                float e1 = __fsub_rn(q1, zr1[d]);
                (&o0.x)[c] = __fadd_rn(zr0[d], e0);
                (&o1.x)[c] = __fadd_rn(zr1[d], e1);
                lsum += (double)__fmul_rn(e0, e0) + (double)__fmul_rn(e1, e1);
            }
            orow0[j] = o0;
            orow1[j] = o1;
        }
    }

    // deterministic block reduction of lsum (double), 4 warps
    #pragma unroll
    for (int o = 16; o > 0; o >>= 1)
        lsum += __shfl_down_sync(0xffffffffu, lsum, o);
    if ((t & 31) == 0) wsm[t >> 5] = lsum;
    __syncthreads();
    if (t == 0) {
        double s = 0.0;
        #pragma unroll
        for (int w = 0; w < THREADS / 32; ++w) s += wsm[w];
        g_partials[b] = s;
    }
}

// ---------------- finish: reduce partials, emit vq_loss ----------------
__global__ void vq_finish(float* __restrict__ out) {
    __shared__ double sm[256];
    int t = threadIdx.x;
    sm[t] = g_partials[t] + g_partials[t + 256];   // NBLOCKS == 512
    __syncthreads();
    #pragma unroll
    for (int s = 128; s > 0; s >>= 1) {
        if (t < s) sm[t] += sm[t + s];
        __syncthreads();
    }
    if (t == 0) {
        float L = (float)(sm[0] / (double)(N_ROWS * DIM));
        // vq_loss = embedding_loss + 0.25 * commitment_loss (numerically equal)
        out[N_ROWS * DIM] = __fadd_rn(L, __fmul_rn(0.25f, L));
    }
}

extern "C" void kernel_launch(void* const* d_in, const int* in_sizes, int n_in,
                              void* d_out, int out_size) {
    const float* z   = (const float*)d_in[0];
    const float* emb = (const float*)d_in[1];
    float* out = (float*)d_out;

    (void)in_sizes; (void)n_in; (void)out_size;

    cudaFuncSetAttribute(vq_main, cudaFuncAttributeMaxDynamicSharedMemorySize, SMEM_BYTES);

    vq_main<<<NBLOCKS, THREADS, SMEM_BYTES>>>(z, emb, out);
    vq_finish<<<1, 256>>>(out);
}